// round 5
// baseline (speedup 1.0000x reference)
#include <cuda_runtime.h>

// x: [N=256, 3, 3, num=256, F=128] fp32, contiguous.
// out: [N, 3, 3, G=128, F=128] fp32.
// For each group g (num pair 2g, 2g+1): winner = candidate with larger
// rotation angle acos(clip((tr-1)/2,-1,1)); acos decreasing => winner is
// candidate with SMALLER clamp(tr,-1,3); ties -> candidate 0 (argmax first-max).

#define N_    256
#define G_    128
#define F4_   32                      // 128 floats = 32 float4
#define TOT   (N_ * G_ * F4_)         // 1,048,576 threads

// strides in float4 units
#define X_STRIDE_D   8192             // 256*128/4   (per (d1*3+d2) step)
#define X_STRIDE_M   32               // 128/4       (per num step)
#define X_STRIDE_N   73728            // 9*8192
#define O_STRIDE_D   4096             // 128*128/4
#define O_STRIDE_G   32
#define O_STRIDE_N   36864            // 9*4096

__device__ __forceinline__ float clamp_tr(float t) {
    return fminf(fmaxf(t, -1.0f), 3.0f);
}

__global__ __launch_bounds__(256, 4)
void Pooling_5866925326754_kernel(const float4* __restrict__ xv,
                                  float4* __restrict__ ov) {
    int idx = blockIdx.x * blockDim.x + threadIdx.x;
    if (idx >= TOT) return;

    int f4 = idx & (F4_ - 1);
    int g  = (idx >> 5) & (G_ - 1);
    int n  = idx >> 12;

    int ib = n * X_STRIDE_N + (2 * g) * X_STRIDE_M + f4;
    int ob = n * O_STRIDE_N + g * O_STRIDE_G + f4;

    // Front-batch all 18 coalesced 128B loads for max MLP.
    float4 a[9], b[9];
#pragma unroll
    for (int d = 0; d < 9; d++) {
        a[d] = xv[ib + d * X_STRIDE_D];
        b[d] = xv[ib + X_STRIDE_M + d * X_STRIDE_D];
    }

    // traces (diagonal positions 0, 4, 8)
    float t0x = a[0].x + a[4].x + a[8].x;
    float t0y = a[0].y + a[4].y + a[8].y;
    float t0z = a[0].z + a[4].z + a[8].z;
    float t0w = a[0].w + a[4].w + a[8].w;
    float t1x = b[0].x + b[4].x + b[8].x;
    float t1y = b[0].y + b[4].y + b[8].y;
    float t1z = b[0].z + b[4].z + b[8].z;
    float t1w = b[0].w + b[4].w + b[8].w;

    // candidate 1 wins only on strictly larger angle == strictly smaller
    // clamped trace (matches argmax first-max tie rule).
    bool sx = clamp_tr(t1x) < clamp_tr(t0x);
    bool sy = clamp_tr(t1y) < clamp_tr(t0y);
    bool sz = clamp_tr(t1z) < clamp_tr(t0z);
    bool sw = clamp_tr(t1w) < clamp_tr(t0w);

#pragma unroll
    for (int d = 0; d < 9; d++) {
        float4 r;
        r.x = sx ? b[d].x : a[d].x;
        r.y = sy ? b[d].y : a[d].y;
        r.z = sz ? b[d].z : a[d].z;
        r.w = sw ? b[d].w : a[d].w;
        ov[ob + d * O_STRIDE_D] = r;
    }
}

extern "C" void kernel_launch(void* const* d_in, const int* in_sizes, int n_in,
                              void* d_out, int out_size) {
    const float4* x = (const float4*)d_in[0];
    float4* out = (float4*)d_out;
    (void)in_sizes; (void)n_in; (void)out_size;
    Pooling_5866925326754_kernel<<<TOT / 256, 256>>>(x, out);
}

// round 6
// speedup vs baseline: 1.0018x; 1.0018x over previous
#include <cuda_runtime.h>

// x: [N=256, 3, 3, num=256, F=128] fp32, contiguous.
// out: [N, 3, 3, G=128, F=128] fp32.
// Winner per pair = larger rotation angle acos(clip((tr-1)/2,-1,1));
// acos decreasing => winner = smaller clamp(tr,-1,3); ties -> candidate 0.
//
// Pure streaming kernel at minimum traffic (453 MB). This revision targets
// achieved-BW efficiency: __ldcs/__stcs evict-first policy (zero reuse, keep
// L2 clean) + diag-first structure so the select mask retires d=0,4,8 early
// and peak register liveness stays ~12 float4 (no 64-reg squeeze).

#define N_    256
#define G_    128
#define F4_   32                      // 128 floats = 32 float4
#define TOT   (N_ * G_ * F4_)         // 1,048,576 threads

// strides in float4 units
#define XSD   8192                    // 256*128/4   per (d1*3+d2) step
#define XSM   32                      // 128/4       per num step
#define XSN   73728                   // 9*8192
#define OSD   4096                    // 128*128/4
#define OSG   32
#define OSN   36864                   // 9*4096

__device__ __forceinline__ float clamp_tr(float t) {
    return fminf(fmaxf(t, -1.0f), 3.0f);
}

__device__ __forceinline__ float4 sel4(bool sx, bool sy, bool sz, bool sw,
                                       const float4& a, const float4& b) {
    float4 r;
    r.x = sx ? b.x : a.x;
    r.y = sy ? b.y : a.y;
    r.z = sz ? b.z : a.z;
    r.w = sw ? b.w : a.w;
    return r;
}

__global__ __launch_bounds__(256, 4)
void Pooling_5866925326754_kernel(const float4* __restrict__ xv,
                                  float4* __restrict__ ov) {
    int idx = blockIdx.x * blockDim.x + threadIdx.x;
    if (idx >= TOT) return;

    int f4 = idx & (F4_ - 1);
    int g  = (idx >> 5) & (G_ - 1);
    int n  = idx >> 12;

    const float4* pa = xv + n * XSN + (2 * g) * XSM + f4;
    const float4* pb = pa + XSM;
    float4*       po = ov + n * OSN + g * OSG + f4;

    // ---- diagonal loads (6), streaming policy ----
    float4 a0 = __ldcs(pa + 0 * XSD);
    float4 a4 = __ldcs(pa + 4 * XSD);
    float4 a8 = __ldcs(pa + 8 * XSD);
    float4 b0 = __ldcs(pb + 0 * XSD);
    float4 b4 = __ldcs(pb + 4 * XSD);
    float4 b8 = __ldcs(pb + 8 * XSD);

    // candidate 1 wins only on strictly smaller clamped trace
    bool sx = clamp_tr(b0.x + b4.x + b8.x) < clamp_tr(a0.x + a4.x + a8.x);
    bool sy = clamp_tr(b0.y + b4.y + b8.y) < clamp_tr(a0.y + a4.y + a8.y);
    bool sz = clamp_tr(b0.z + b4.z + b8.z) < clamp_tr(a0.z + a4.z + a8.z);
    bool sw = clamp_tr(b0.w + b4.w + b8.w) < clamp_tr(a0.w + a4.w + a8.w);

    // retire the diagonal positions immediately (frees 6 float4 of liveness)
    __stcs(po + 0 * OSD, sel4(sx, sy, sz, sw, a0, b0));
    __stcs(po + 4 * OSD, sel4(sx, sy, sz, sw, a4, b4));
    __stcs(po + 8 * OSD, sel4(sx, sy, sz, sw, a8, b8));

    // ---- off-diagonal positions: 1,2,3,5,6,7 ----
    float4 a1 = __ldcs(pa + 1 * XSD);
    float4 a2 = __ldcs(pa + 2 * XSD);
    float4 a3 = __ldcs(pa + 3 * XSD);
    float4 a5 = __ldcs(pa + 5 * XSD);
    float4 a6 = __ldcs(pa + 6 * XSD);
    float4 a7 = __ldcs(pa + 7 * XSD);
    float4 b1 = __ldcs(pb + 1 * XSD);
    float4 b2 = __ldcs(pb + 2 * XSD);
    float4 b3 = __ldcs(pb + 3 * XSD);
    float4 b5 = __ldcs(pb + 5 * XSD);
    float4 b6 = __ldcs(pb + 6 * XSD);
    float4 b7 = __ldcs(pb + 7 * XSD);

    __stcs(po + 1 * OSD, sel4(sx, sy, sz, sw, a1, b1));
    __stcs(po + 2 * OSD, sel4(sx, sy, sz, sw, a2, b2));
    __stcs(po + 3 * OSD, sel4(sx, sy, sz, sw, a3, b3));
    __stcs(po + 5 * OSD, sel4(sx, sy, sz, sw, a5, b5));
    __stcs(po + 6 * OSD, sel4(sx, sy, sz, sw, a6, b6));
    __stcs(po + 7 * OSD, sel4(sx, sy, sz, sw, a7, b7));
}

extern "C" void kernel_launch(void* const* d_in, const int* in_sizes, int n_in,
                              void* d_out, int out_size) {
    const float4* x = (const float4*)d_in[0];
    float4* out = (float4*)d_out;
    (void)in_sizes; (void)n_in; (void)out_size;
    Pooling_5866925326754_kernel<<<TOT / 256, 256>>>(x, out);
}